// round 14
// baseline (speedup 1.0000x reference)
#include <cuda_runtime.h>
#include <cuda_fp16.h>
#include <math.h>
#include <stdint.h>

#define N      8192
#define DIM    128
#define NCLS   64
#define BM     128
#define NT     (N / BM)          // 64
#define NGRP   8
#define KT     8
#define NSLOT  (NT + NGRP)       // 72
#define MAXM   256
#define L2E    1.4426950408889634f
#define LN2    0.6931471805599453f

#define PITCHB 272
#define TILE_BYTES (128 * PITCHB)

#define OFF_RCI    0
#define OFF_CCJ0   512
#define OFF_CCJ1   1024
#define OFF_COLRED 1536
#define OFF_AH     2048
#define OFF_BH0    (OFF_AH + TILE_BYTES)
#define OFF_BH1    (OFF_BH0 + TILE_BYTES)
#define Z_SMEM_Z   (OFF_BH1 + TILE_BYTES)   // 106496 -> occ 2

// ---------------- helpers ----------------
__device__ __forceinline__ uint32_t smem_u32(const void* p) {
    uint32_t a;
    asm("{ .reg .u64 t; cvta.to.shared.u64 t, %1; cvt.u32.u64 %0, t; }" : "=r"(a) : "l"(p));
    return a;
}
__device__ __forceinline__ float ex2(float x) {
    float y;
    asm("ex2.approx.ftz.f32 %0, %1;" : "=f"(y) : "f"(x));
    return y;
}
__device__ __forceinline__ float lg2(float x) {
    float y;
    asm("lg2.approx.ftz.f32 %0, %1;" : "=f"(y) : "f"(x));
    return y;
}
__device__ __forceinline__ uint32_t pack_ex2_f16x2(float hi, float lo) {
    uint32_t h, e;
    asm("cvt.rn.f16x2.f32 %0, %1, %2;" : "=r"(h) : "f"(hi), "f"(lo));
    asm("ex2.approx.f16x2 %0, %1;" : "=r"(e) : "r"(h));
    return e;
}
__device__ __forceinline__ uint32_t hadd2u(uint32_t a, uint32_t b) {
    uint32_t d;
    asm("add.rn.f16x2 %0, %1, %2;" : "=r"(d) : "r"(a), "r"(b));
    return d;
}
__device__ __forceinline__ float2 f16x2_to_f2(uint32_t v) {
    __half2 h = *reinterpret_cast<__half2*>(&v);
    return __half22float2(h);
}

#define CP_ASYNC16(dst, src) \
    asm volatile("cp.async.cg.shared.global [%0], [%1], 16;" :: "r"(dst), "l"(src))
#define CP_COMMIT()  asm volatile("cp.async.commit_group;" ::: "memory")
#define CP_WAIT(n)   asm volatile("cp.async.wait_group %0;" :: "n"(n) : "memory")

#define LDSM4(r, addr) \
    asm volatile("ldmatrix.sync.aligned.m8n8.x4.shared.b16 {%0,%1,%2,%3}, [%4];" \
        : "=r"((r)[0]), "=r"((r)[1]), "=r"((r)[2]), "=r"((r)[3]) : "r"(addr))

__device__ __forceinline__ void mma16816(float* c, const uint32_t* a,
                                         uint32_t b0, uint32_t b1) {
    asm volatile(
        "mma.sync.aligned.m16n8k16.row.col.f32.f16.f16.f32 "
        "{%0,%1,%2,%3}, {%4,%5,%6,%7}, {%8,%9}, {%0,%1,%2,%3};"
        : "+f"(c[0]), "+f"(c[1]), "+f"(c[2]), "+f"(c[3])
        : "r"(a[0]), "r"(a[1]), "r"(a[2]), "r"(a[3]), "r"(b0), "r"(b1));
}

// ---------------- scratch ----------------
__device__ __half g_embA[N * DIM];
__device__ __half g_embB[N * DIM];
__device__ float g_csqP[N];
__device__ int   g_cnt[NCLS];
__device__ int   g_off[NCLS + 1];
__device__ int   g_rank[N];
__device__ int   g_slotcls[N];
__device__ float g_Zmat[NSLOT][N];
__device__ float g_S[N];
__device__ float g_Dpair[NCLS][MAXM][MAXM];
__device__ float g_rowsum[N];

// ---------------- classes ----------------
__global__ __launch_bounds__(256)
void classes_kernel(const int* __restrict__ labels) {
    const int c = blockIdx.x;
    const int tid = threadIdx.x, warp = tid >> 5, lane = tid & 31;
    __shared__ int segcnt[8];

    const int base0 = warp * 1024;
    int cnt = 0;
#pragma unroll 4
    for (int it = 0; it < 32; ++it) {
        int l = labels[base0 + it * 32 + lane];
        cnt += __popc(__ballot_sync(0xffffffffu, l == c));
    }
    if (lane == 0) segcnt[warp] = cnt;
    __syncthreads();
    int segoff = 0;
    for (int k = 0; k < warp; ++k) segoff += segcnt[k];
    cnt = segoff;
#pragma unroll 4
    for (int it = 0; it < 32; ++it) {
        int i = base0 + it * 32 + lane;
        bool mine = (labels[i] == c);
        unsigned mask = __ballot_sync(0xffffffffu, mine);
        if (mine) g_rank[i] = cnt + __popc(mask & ((1u << lane) - 1u));
        cnt += __popc(mask);
    }
    if (warp == 7 && lane == 0) g_cnt[c] = cnt;
}

// ---------------- prep ----------------
__global__ __launch_bounds__(256)
void prep_kernel(const float* __restrict__ emb, const int* __restrict__ labels) {
    __shared__ int s_off[NCLS + 1];
    const int tid  = threadIdx.x;
    const int gt   = blockIdx.x * blockDim.x + tid;
    const int r    = gt >> 5;
    const int lane = tid & 31;
    const float ASCALE = -2.f * L2E;

    if (tid < NCLS) s_off[tid + 1] = g_cnt[tid];
    if (gt < (NSLOT * N) / 4)
        reinterpret_cast<float4*>(g_Zmat)[gt] = make_float4(0.f, 0.f, 0.f, 0.f);
    __syncthreads();
    if (tid == 0) {
        s_off[0] = 0;
        for (int c = 1; c <= NCLS; ++c) s_off[c] += s_off[c - 1];
    }
    __syncthreads();
    if (blockIdx.x == 0 && tid <= NCLS) g_off[tid] = s_off[tid];

    float4 v = reinterpret_cast<const float4*>(emb + (size_t)r * DIM)[lane];
    float s = v.x * v.x + v.y * v.y + v.z * v.z + v.w * v.w;
#pragma unroll
    for (int off = 16; off > 0; off >>= 1)
        s += __shfl_xor_sync(0xffffffffu, s, off);

    const int lab  = labels[r];
    const int slot = s_off[lab] + g_rank[r];
    if (lane == 0) {
        g_csqP[slot]    = s * L2E;
        g_slotcls[slot] = lab;
    }
    reinterpret_cast<__half2*>(g_embB + (size_t)slot * DIM)[lane * 2 + 0] = __floats2half2_rn(v.x, v.y);
    reinterpret_cast<__half2*>(g_embB + (size_t)slot * DIM)[lane * 2 + 1] = __floats2half2_rn(v.z, v.w);
    reinterpret_cast<__half2*>(g_embA + (size_t)slot * DIM)[lane * 2 + 0] = __floats2half2_rn(v.x * ASCALE, v.y * ASCALE);
    reinterpret_cast<__half2*>(g_embA + (size_t)slot * DIM)[lane * 2 + 1] = __floats2half2_rn(v.z * ASCALE, v.w * ASCALE);
}

// ---------------- zc kernel: y==0 -> per-class correction; y=1..NGRP -> z strips ----
__global__ __launch_bounds__(256, 2)
void zc_kernel() {
    extern __shared__ char sm[];
    float*    rci     = reinterpret_cast<float*>(sm + OFF_RCI);
    float*    ccj0    = reinterpret_cast<float*>(sm + OFF_CCJ0);
    float*    ccj1    = reinterpret_cast<float*>(sm + OFF_CCJ1);
    uint32_t* colred2 = reinterpret_cast<uint32_t*>(sm + OFF_COLRED);
    const uint32_t smb = smem_u32(sm);

    const int tid  = threadIdx.x;
    const int lane = tid & 31;
    const int wid  = tid >> 5;
    const int warp_m = wid & 1;
    const int warp_n = wid >> 1;
    const int gq = lane >> 2;
    const int t  = lane & 3;

    const int mtx = lane >> 3, lrow = lane & 7;
    const uint32_t aoff = (uint32_t)((warp_m * 64 + (mtx & 1) * 8 + lrow) * PITCHB
                                     + ((mtx >> 1) * 8) * 2);
    const uint32_t boff = (uint32_t)((warp_n * 32 + (mtx >> 1) * 8 + lrow) * PITCHB
                                     + ((mtx & 1) * 8) * 2);
    const uint32_t aAh = smb + OFF_AH + aoff;

    if (blockIdx.y == 0) {
        // ======== per-class correction path (first in block order) ========
        const int c    = blockIdx.x;
        const int base = g_off[c];
        const int m    = g_off[c + 1] - base;
        if (m <= 0) return;
        const int ntc  = (m + 127) / 128;
        const uint32_t aBh = smb + OFF_BH0 + boff;

        for (int ti = 0; ti < ntc; ++ti) {
            const int ri = ti * 128;
            __syncthreads();
            for (int s = tid; s < 2048; s += 256) {
                int row = s >> 4, ch = s & 15;
                uint4 v = make_uint4(0, 0, 0, 0);
                if (ri + row < m)
                    v = *reinterpret_cast<const uint4*>(g_embA + (size_t)(base + ri + row) * DIM + ch * 8);
                *reinterpret_cast<uint4*>(sm + OFF_AH + row * PITCHB + ch * 16) = v;
            }
            if (tid < BM) rci[tid] = (ri + tid < m) ? g_csqP[base + ri + tid] : 0.f;

            float rowacc[8];
#pragma unroll
            for (int i = 0; i < 8; ++i) rowacc[i] = 0.f;

            for (int tj = 0; tj < ntc; ++tj) {
                const int rj = tj * 128;
                __syncthreads();
                for (int s = tid; s < 2048; s += 256) {
                    int row = s >> 4, ch = s & 15;
                    uint4 w = make_uint4(0, 0, 0, 0);
                    if (rj + row < m)
                        w = *reinterpret_cast<const uint4*>(g_embB + (size_t)(base + rj + row) * DIM + ch * 8);
                    *reinterpret_cast<uint4*>(sm + OFF_BH0 + row * PITCHB + ch * 16) = w;
                }
                if (tid < BM) ccj0[tid] = (rj + tid < m) ? g_csqP[base + rj + tid] : 0.f;
                __syncthreads();

                float acc[16][4];
#pragma unroll
                for (int i = 0; i < 16; ++i)
#pragma unroll
                    for (int j = 0; j < 4; ++j) acc[i][j] = 0.f;
#pragma unroll
                for (int ks = 0; ks < 8; ++ks) {
                    const uint32_t kb = (uint32_t)ks * 32;
                    uint32_t ah[4][4], bh[2][4];
#pragma unroll
                    for (int am = 0; am < 4; ++am)
                        LDSM4(ah[am], aAh + (uint32_t)am * (16 * PITCHB) + kb);
#pragma unroll
                    for (int bn = 0; bn < 2; ++bn)
                        LDSM4(bh[bn], aBh + (uint32_t)bn * (16 * PITCHB) + kb);
#pragma unroll
                    for (int am = 0; am < 4; ++am)
#pragma unroll
                        for (int na = 0; na < 4; ++na) {
                            const int bn = na >> 1, p = (na & 1) * 2;
                            mma16816(acc[am * 4 + na], ah[am], bh[bn][p], bh[bn][p + 1]);
                        }
                }
#pragma unroll
                for (int am = 0; am < 4; ++am)
#pragma unroll
                    for (int h = 0; h < 2; ++h) {
                        const int rr = am * 2 + h;
                        const int mloc = warp_m * 64 + am * 16 + h * 8 + gq;
                        const int p = ri + mloc;
                        const float civ = rci[mloc];
#pragma unroll
                        for (int na = 0; na < 4; ++na)
#pragma unroll
                            for (int cc = 0; cc < 2; ++cc) {
                                int col = warp_n * 32 + na * 8 + 2 * t + cc;
                                int q = rj + col;
                                if (p < m && q < m) {
                                    float tv = acc[am * 4 + na][h * 2 + cc] + ccj0[col] + civ;
                                    rowacc[rr] += ex2(tv);
                                    if (q > p) g_Dpair[c][p][q] = ex2(-tv);
                                }
                            }
                    }
            }

            __syncthreads();
            float* red = reinterpret_cast<float*>(sm + OFF_BH0);
#pragma unroll
            for (int am = 0; am < 4; ++am)
#pragma unroll
                for (int h = 0; h < 2; ++h) {
                    int mloc = warp_m * 64 + am * 16 + h * 8 + gq;
                    red[mloc * 17 + warp_n * 4 + t] = rowacc[am * 2 + h];
                }
            __syncthreads();
            if (tid < BM && ri + tid < m) {
                float s = 0.f;
#pragma unroll
                for (int q = 0; q < 16; ++q) s += red[tid * 17 + q];
                g_S[base + ri + tid] = s;
            }
        }
        return;
    }

    // ======== z strip path ========
    const int bi = blockIdx.x;
    const int gr = blockIdx.y - 1;
    if (bi >= KT * gr + KT) return;
    const int lo = (bi > KT * gr) ? bi : KT * gr;
    const int hi = KT * gr + KT;

    const int r0 = bi * BM;
    const uint32_t bufB[2] = {smb + OFF_BH0, smb + OFF_BH1};
    float* ccjb[2] = {ccj0, ccj1};

    for (int s = tid; s < 2048; s += 256) {
        int row = s >> 4, ch = s & 15;
        CP_ASYNC16(smb + OFF_AH + (uint32_t)(row * PITCHB + ch * 16),
                   g_embA + (size_t)(r0 + row) * DIM + ch * 8);
    }
    if (tid < BM) rci[tid] = g_csqP[r0 + tid];

    for (int s = tid; s < 2048; s += 256) {
        int row = s >> 4, ch = s & 15;
        CP_ASYNC16(bufB[0] + (uint32_t)(row * PITCHB + ch * 16),
                   g_embB + (size_t)(lo * BM + row) * DIM + ch * 8);
    }
    if (tid < BM) ccj0[tid] = g_csqP[lo * BM + tid];
    CP_COMMIT();

    uint32_t rowacc2[8];
#pragma unroll
    for (int i = 0; i < 8; ++i) rowacc2[i] = 0u;

    for (int bj = lo; bj < hi; ++bj) {
        const int cur = (bj - lo) & 1;
        const int c0 = bj * BM;
        const bool offdiag = (bj != bi);

        if (bj + 1 < hi) {
            const int nc0 = (bj + 1) * BM;
            for (int s = tid; s < 2048; s += 256) {
                int row = s >> 4, ch = s & 15;
                CP_ASYNC16(bufB[cur ^ 1] + (uint32_t)(row * PITCHB + ch * 16),
                           g_embB + (size_t)(nc0 + row) * DIM + ch * 8);
            }
            if (tid < BM) ccjb[cur ^ 1][tid] = g_csqP[nc0 + tid];
            CP_COMMIT();
            CP_WAIT(1);
        } else {
            CP_WAIT(0);
        }
        __syncthreads();

        const uint32_t aBh = bufB[cur] + boff;
        const float* ccj = ccjb[cur];

        float acc[16][4];
#pragma unroll
        for (int i = 0; i < 16; ++i)
#pragma unroll
            for (int j = 0; j < 4; ++j) acc[i][j] = 0.f;

#pragma unroll
        for (int ks = 0; ks < 8; ++ks) {
            const uint32_t kb = (uint32_t)ks * 32;
            uint32_t ah[4][4], bh[2][4];
#pragma unroll
            for (int am = 0; am < 4; ++am)
                LDSM4(ah[am], aAh + (uint32_t)am * (16 * PITCHB) + kb);
#pragma unroll
            for (int bn = 0; bn < 2; ++bn)
                LDSM4(bh[bn], aBh + (uint32_t)bn * (16 * PITCHB) + kb);
#pragma unroll
            for (int am = 0; am < 4; ++am)
#pragma unroll
                for (int na = 0; na < 4; ++na) {
                    const int bn = na >> 1, p = (na & 1) * 2;
                    mma16816(acc[am * 4 + na], ah[am], bh[bn][p], bh[bn][p + 1]);
                }
        }

        uint32_t colacc2[4] = {0u, 0u, 0u, 0u};
        float cjv[8];
#pragma unroll
        for (int na = 0; na < 4; ++na)
#pragma unroll
            for (int cc = 0; cc < 2; ++cc)
                cjv[na * 2 + cc] = ccj[warp_n * 32 + na * 8 + 2 * t + cc];

#pragma unroll
        for (int am = 0; am < 4; ++am)
#pragma unroll
            for (int h = 0; h < 2; ++h) {
                const int rr = am * 2 + h;
                const float civ = rci[warp_m * 64 + am * 16 + h * 8 + gq];
                float pc[8];
#pragma unroll
                for (int i = 0; i < 8; ++i) pc[i] = cjv[i] + civ;
                uint32_t racc2 = rowacc2[rr];
#pragma unroll
                for (int na = 0; na < 4; ++na) {
                    float tv0 = acc[am * 4 + na][h * 2 + 0] + pc[na * 2 + 0];
                    float tv1 = acc[am * 4 + na][h * 2 + 1] + pc[na * 2 + 1];
                    uint32_t e2 = pack_ex2_f16x2(tv1, tv0);
                    racc2 = hadd2u(racc2, e2);
                    colacc2[na] = hadd2u(colacc2[na], e2);
                }
                rowacc2[rr] = racc2;
            }

        if (offdiag) {
#pragma unroll
            for (int i = 0; i < 4; ++i)
#pragma unroll
                for (int off = 4; off < 32; off <<= 1)
                    colacc2[i] = hadd2u(colacc2[i],
                                        __shfl_xor_sync(0xffffffffu, colacc2[i], off));
            if (warp_m == 0 && gq == 0) {
#pragma unroll
                for (int na = 0; na < 4; ++na)
                    colred2[warp_n * 16 + na * 4 + t] = colacc2[na];
            }
        }
        __syncthreads();
        if (offdiag && warp_m == 1 && gq == 0) {
#pragma unroll
            for (int na = 0; na < 4; ++na) {
                uint32_t s2 = hadd2u(colred2[warp_n * 16 + na * 4 + t], colacc2[na]);
                float2 f = f16x2_to_f2(s2);
                int col = warp_n * 32 + na * 8 + 2 * t;
                *reinterpret_cast<float2*>(&g_Zmat[bi][c0 + col]) = f;
            }
        }
    }

    __syncthreads();
    float* red = reinterpret_cast<float*>(sm + OFF_BH0);
#pragma unroll
    for (int am = 0; am < 4; ++am)
#pragma unroll
        for (int h = 0; h < 2; ++h) {
            int mloc = warp_m * 64 + am * 16 + h * 8 + gq;
            float2 f = f16x2_to_f2(rowacc2[am * 2 + h]);
            red[mloc * 17 + warp_n * 4 + t] = f.x + f.y;
        }
    __syncthreads();
    if (tid < BM) {
        float s = 0.f;
#pragma unroll
        for (int q = 0; q < 16; ++q) s += red[tid * 17 + q];
        g_Zmat[NT + gr][r0 + tid] = s;
    }
}

// ---------------- pair kernel: 64 blocks, coalesced Za reduce + pair loop ---------
__global__ __launch_bounds__(512)
void pair4_kernel() {
    __shared__ float sred[4][128];
    __shared__ float sZa[128];
    const int tid  = threadIdx.x;
    const int base = blockIdx.x * 128;
    const int ls   = tid & 127;
    const int grp  = tid >> 7;    // 0..3

    // phase 1: coalesced Zmat column sums (72 slots split 4x18)
    float a = 0.f;
#pragma unroll 6
    for (int sl = grp * 18; sl < grp * 18 + 18; ++sl)
        a += g_Zmat[sl][base + ls];
    sred[grp][ls] = a;
    __syncthreads();
    if (grp == 0)
        sZa[ls] = (sred[0][ls] + sred[1][ls]) + (sred[2][ls] + sred[3][ls]) - g_S[base + ls];
    __syncthreads();

    // phase 2: 16 warps x 8 slots
    const int warp = tid >> 5, lane = tid & 31;
#pragma unroll
    for (int k = 0; k < 8; ++k) {
        const int s  = base + warp * 8 + k;
        const int c  = g_slotcls[s];
        const int p  = s - g_off[c];
        const int m  = g_off[c + 1] - g_off[c];
        const float Za = sZa[warp * 8 + k];
        float lsum = 0.f;
        for (int q = p + 1 + lane; q < m; q += 32)
            lsum += lg2(fmaf(Za, g_Dpair[c][p][q], 1.0f));
        lsum *= LN2;
#pragma unroll
        for (int off = 16; off > 0; off >>= 1)
            lsum += __shfl_xor_sync(0xffffffffu, lsum, off);
        if (lane == 0) g_rowsum[s] = lsum;
    }
}

// ---------------- finish ----------------
__global__ __launch_bounds__(512)
void finish_kernel(float* __restrict__ out) {
    __shared__ float smean[NCLS];
    __shared__ int   svalid[NCLS];
    const int tid = threadIdx.x, warp = tid >> 5, lane = tid & 31;

    for (int c = warp * 4; c < warp * 4 + 4; ++c) {
        const int base = g_off[c];
        const int m = g_off[c + 1] - base;
        float s = 0.f;
        for (int q = lane; q < m; q += 32) s += g_rowsum[base + q];
#pragma unroll
        for (int off = 16; off > 0; off >>= 1)
            s += __shfl_xor_sync(0xffffffffu, s, off);
        if (lane == 0) {
            if (m >= 2) {
                smean[c]  = s / (0.5f * (float)m * (float)(m - 1));
                svalid[c] = 1;
            } else { smean[c] = 0.f; svalid[c] = 0; }
        }
    }
    __syncthreads();
    if (warp == 0) {
        float s  = smean[lane] + smean[lane + 32];
        int   nv = svalid[lane] + svalid[lane + 32];
#pragma unroll
        for (int off = 16; off > 0; off >>= 1) {
            s  += __shfl_xor_sync(0xffffffffu, s, off);
            nv += __shfl_xor_sync(0xffffffffu, nv, off);
        }
        if (lane == 0) out[0] = s / (float)(nv > 0 ? nv : 1);
    }
}

// ---------------- launch ----------------
extern "C" void kernel_launch(void* const* d_in, const int* in_sizes, int n_in,
                              void* d_out, int out_size) {
    const float* emb    = (const float*)d_in[0];
    const int*   labels = (const int*)d_in[1];
    float*       out    = (float*)d_out;

    static bool attr_set = false;
    if (!attr_set) {
        cudaFuncSetAttribute(zc_kernel, cudaFuncAttributeMaxDynamicSharedMemorySize, Z_SMEM_Z);
        attr_set = true;
    }

    classes_kernel<<<NCLS, 256>>>(labels);
    prep_kernel<<<N / 8, 256>>>(emb, labels);
    zc_kernel<<<dim3(NT, NGRP + 1), 256, Z_SMEM_Z>>>();
    pair4_kernel<<<NCLS, 512>>>();
    finish_kernel<<<1, 512>>>(out);
}

// round 15
// speedup vs baseline: 1.1455x; 1.1455x over previous
#include <cuda_runtime.h>
#include <cuda_fp16.h>
#include <math.h>
#include <stdint.h>

#define N      8192
#define DIM    128
#define NCLS   64
#define BM     128
#define NT     (N / BM)          // 64
#define NGRP   8
#define KT     8
#define NSLOT  (NT + NGRP)       // 72
#define SLOTP  80                // padded slots per row
#define MAXM   256
#define L2E    1.4426950408889634f
#define LN2    0.6931471805599453f

#define PITCHB 272
#define TILE_BYTES (128 * PITCHB)

#define OFF_RCI    0
#define OFF_CCJ0   512
#define OFF_CCJ1   1024
#define OFF_COLRED 1536
#define OFF_AH     2048
#define OFF_BH0    (OFF_AH + TILE_BYTES)
#define OFF_BH1    (OFF_BH0 + TILE_BYTES)
#define Z_SMEM_Z   (OFF_BH1 + TILE_BYTES)   // 106496 -> occ 2

// ---------------- helpers ----------------
__device__ __forceinline__ uint32_t smem_u32(const void* p) {
    uint32_t a;
    asm("{ .reg .u64 t; cvta.to.shared.u64 t, %1; cvt.u32.u64 %0, t; }" : "=r"(a) : "l"(p));
    return a;
}
__device__ __forceinline__ float ex2(float x) {
    float y;
    asm("ex2.approx.ftz.f32 %0, %1;" : "=f"(y) : "f"(x));
    return y;
}
__device__ __forceinline__ float lg2(float x) {
    float y;
    asm("lg2.approx.ftz.f32 %0, %1;" : "=f"(y) : "f"(x));
    return y;
}
__device__ __forceinline__ uint32_t pack_ex2_f16x2(float hi, float lo) {
    uint32_t h, e;
    asm("cvt.rn.f16x2.f32 %0, %1, %2;" : "=r"(h) : "f"(hi), "f"(lo));
    asm("ex2.approx.f16x2 %0, %1;" : "=r"(e) : "r"(h));
    return e;
}
__device__ __forceinline__ uint32_t hadd2u(uint32_t a, uint32_t b) {
    uint32_t d;
    asm("add.rn.f16x2 %0, %1, %2;" : "=r"(d) : "r"(a), "r"(b));
    return d;
}
__device__ __forceinline__ float2 f16x2_to_f2(uint32_t v) {
    __half2 h = *reinterpret_cast<__half2*>(&v);
    return __half22float2(h);
}

#define CP_ASYNC16(dst, src) \
    asm volatile("cp.async.cg.shared.global [%0], [%1], 16;" :: "r"(dst), "l"(src))
#define CP_COMMIT()  asm volatile("cp.async.commit_group;" ::: "memory")
#define CP_WAIT(n)   asm volatile("cp.async.wait_group %0;" :: "n"(n) : "memory")

#define LDSM4(r, addr) \
    asm volatile("ldmatrix.sync.aligned.m8n8.x4.shared.b16 {%0,%1,%2,%3}, [%4];" \
        : "=r"((r)[0]), "=r"((r)[1]), "=r"((r)[2]), "=r"((r)[3]) : "r"(addr))

__device__ __forceinline__ void mma16816(float* c, const uint32_t* a,
                                         uint32_t b0, uint32_t b1) {
    asm volatile(
        "mma.sync.aligned.m16n8k16.row.col.f32.f16.f16.f32 "
        "{%0,%1,%2,%3}, {%4,%5,%6,%7}, {%8,%9}, {%0,%1,%2,%3};"
        : "+f"(c[0]), "+f"(c[1]), "+f"(c[2]), "+f"(c[3])
        : "r"(a[0]), "r"(a[1]), "r"(a[2]), "r"(a[3]), "r"(b0), "r"(b1));
}

// ---------------- scratch ----------------
__device__ __half g_embA[N * DIM];
__device__ __half g_embB[N * DIM];
__device__ float g_csqP[N];
__device__ int   g_cnt[NCLS];
__device__ int   g_off[NCLS + 1];
__device__ int   g_rank[N];
__device__ int   g_slotcls[N];
__device__ float g_Zmat[N][SLOTP];   // TRANSPOSED: [anchor][slot], padded to 80
__device__ float g_S[N];
__device__ float g_Dpair[NCLS][MAXM][MAXM];
__device__ float g_rowsum[N];

// ---------------- classes ----------------
__global__ __launch_bounds__(256)
void classes_kernel(const int* __restrict__ labels) {
    const int c = blockIdx.x;
    const int tid = threadIdx.x, warp = tid >> 5, lane = tid & 31;
    __shared__ int segcnt[8];

    const int base0 = warp * 1024;
    int cnt = 0;
#pragma unroll 4
    for (int it = 0; it < 32; ++it) {
        int l = labels[base0 + it * 32 + lane];
        cnt += __popc(__ballot_sync(0xffffffffu, l == c));
    }
    if (lane == 0) segcnt[warp] = cnt;
    __syncthreads();
    int segoff = 0;
    for (int k = 0; k < warp; ++k) segoff += segcnt[k];
    cnt = segoff;
#pragma unroll 4
    for (int it = 0; it < 32; ++it) {
        int i = base0 + it * 32 + lane;
        bool mine = (labels[i] == c);
        unsigned mask = __ballot_sync(0xffffffffu, mine);
        if (mine) g_rank[i] = cnt + __popc(mask & ((1u << lane) - 1u));
        cnt += __popc(mask);
    }
    if (warp == 7 && lane == 0) g_cnt[c] = cnt;
}

// ---------------- prep ----------------
__global__ __launch_bounds__(256)
void prep_kernel(const float* __restrict__ emb, const int* __restrict__ labels) {
    __shared__ int s_off[NCLS + 1];
    const int tid  = threadIdx.x;
    const int gt   = blockIdx.x * blockDim.x + tid;
    const int r    = gt >> 5;
    const int lane = tid & 31;
    const float ASCALE = -2.f * L2E;

    if (tid < NCLS) s_off[tid + 1] = g_cnt[tid];
    if (gt < (N * SLOTP) / 4)
        reinterpret_cast<float4*>(g_Zmat)[gt] = make_float4(0.f, 0.f, 0.f, 0.f);
    __syncthreads();
    if (tid == 0) {
        s_off[0] = 0;
        for (int c = 1; c <= NCLS; ++c) s_off[c] += s_off[c - 1];
    }
    __syncthreads();
    if (blockIdx.x == 0 && tid <= NCLS) g_off[tid] = s_off[tid];

    float4 v = reinterpret_cast<const float4*>(emb + (size_t)r * DIM)[lane];
    float s = v.x * v.x + v.y * v.y + v.z * v.z + v.w * v.w;
#pragma unroll
    for (int off = 16; off > 0; off >>= 1)
        s += __shfl_xor_sync(0xffffffffu, s, off);

    const int lab  = labels[r];
    const int slot = s_off[lab] + g_rank[r];
    if (lane == 0) {
        g_csqP[slot]    = s * L2E;
        g_slotcls[slot] = lab;
    }
    reinterpret_cast<__half2*>(g_embB + (size_t)slot * DIM)[lane * 2 + 0] = __floats2half2_rn(v.x, v.y);
    reinterpret_cast<__half2*>(g_embB + (size_t)slot * DIM)[lane * 2 + 1] = __floats2half2_rn(v.z, v.w);
    reinterpret_cast<__half2*>(g_embA + (size_t)slot * DIM)[lane * 2 + 0] = __floats2half2_rn(v.x * ASCALE, v.y * ASCALE);
    reinterpret_cast<__half2*>(g_embA + (size_t)slot * DIM)[lane * 2 + 1] = __floats2half2_rn(v.z * ASCALE, v.w * ASCALE);
}

// ---------------- zc kernel: y==0 -> per-class correction; y=1..NGRP -> z strips ----
__global__ __launch_bounds__(256, 2)
void zc_kernel() {
    extern __shared__ char sm[];
    float*    rci     = reinterpret_cast<float*>(sm + OFF_RCI);
    float*    ccj0    = reinterpret_cast<float*>(sm + OFF_CCJ0);
    float*    ccj1    = reinterpret_cast<float*>(sm + OFF_CCJ1);
    uint32_t* colred2 = reinterpret_cast<uint32_t*>(sm + OFF_COLRED);
    const uint32_t smb = smem_u32(sm);

    const int tid  = threadIdx.x;
    const int lane = tid & 31;
    const int wid  = tid >> 5;
    const int warp_m = wid & 1;
    const int warp_n = wid >> 1;
    const int gq = lane >> 2;
    const int t  = lane & 3;

    const int mtx = lane >> 3, lrow = lane & 7;
    const uint32_t aoff = (uint32_t)((warp_m * 64 + (mtx & 1) * 8 + lrow) * PITCHB
                                     + ((mtx >> 1) * 8) * 2);
    const uint32_t boff = (uint32_t)((warp_n * 32 + (mtx >> 1) * 8 + lrow) * PITCHB
                                     + ((mtx & 1) * 8) * 2);
    const uint32_t aAh = smb + OFF_AH + aoff;

    if (blockIdx.y == 0) {
        // ======== per-class correction path (first in block order) ========
        const int c    = blockIdx.x;
        const int base = g_off[c];
        const int m    = g_off[c + 1] - base;
        if (m <= 0) return;
        const int ntc  = (m + 127) / 128;
        const uint32_t aBh = smb + OFF_BH0 + boff;

        for (int ti = 0; ti < ntc; ++ti) {
            const int ri = ti * 128;
            __syncthreads();
            for (int s = tid; s < 2048; s += 256) {
                int row = s >> 4, ch = s & 15;
                uint4 v = make_uint4(0, 0, 0, 0);
                if (ri + row < m)
                    v = *reinterpret_cast<const uint4*>(g_embA + (size_t)(base + ri + row) * DIM + ch * 8);
                *reinterpret_cast<uint4*>(sm + OFF_AH + row * PITCHB + ch * 16) = v;
            }
            if (tid < BM) rci[tid] = (ri + tid < m) ? g_csqP[base + ri + tid] : 0.f;

            float rowacc[8];
#pragma unroll
            for (int i = 0; i < 8; ++i) rowacc[i] = 0.f;

            for (int tj = 0; tj < ntc; ++tj) {
                const int rj = tj * 128;
                __syncthreads();
                for (int s = tid; s < 2048; s += 256) {
                    int row = s >> 4, ch = s & 15;
                    uint4 w = make_uint4(0, 0, 0, 0);
                    if (rj + row < m)
                        w = *reinterpret_cast<const uint4*>(g_embB + (size_t)(base + rj + row) * DIM + ch * 8);
                    *reinterpret_cast<uint4*>(sm + OFF_BH0 + row * PITCHB + ch * 16) = w;
                }
                if (tid < BM) ccj0[tid] = (rj + tid < m) ? g_csqP[base + rj + tid] : 0.f;
                __syncthreads();

                float acc[16][4];
#pragma unroll
                for (int i = 0; i < 16; ++i)
#pragma unroll
                    for (int j = 0; j < 4; ++j) acc[i][j] = 0.f;
#pragma unroll
                for (int ks = 0; ks < 8; ++ks) {
                    const uint32_t kb = (uint32_t)ks * 32;
                    uint32_t ah[4][4], bh[2][4];
#pragma unroll
                    for (int am = 0; am < 4; ++am)
                        LDSM4(ah[am], aAh + (uint32_t)am * (16 * PITCHB) + kb);
#pragma unroll
                    for (int bn = 0; bn < 2; ++bn)
                        LDSM4(bh[bn], aBh + (uint32_t)bn * (16 * PITCHB) + kb);
#pragma unroll
                    for (int am = 0; am < 4; ++am)
#pragma unroll
                        for (int na = 0; na < 4; ++na) {
                            const int bn = na >> 1, p = (na & 1) * 2;
                            mma16816(acc[am * 4 + na], ah[am], bh[bn][p], bh[bn][p + 1]);
                        }
                }
#pragma unroll
                for (int am = 0; am < 4; ++am)
#pragma unroll
                    for (int h = 0; h < 2; ++h) {
                        const int rr = am * 2 + h;
                        const int mloc = warp_m * 64 + am * 16 + h * 8 + gq;
                        const int p = ri + mloc;
                        const float civ = rci[mloc];
#pragma unroll
                        for (int na = 0; na < 4; ++na)
#pragma unroll
                            for (int cc = 0; cc < 2; ++cc) {
                                int col = warp_n * 32 + na * 8 + 2 * t + cc;
                                int q = rj + col;
                                if (p < m && q < m) {
                                    float tv = acc[am * 4 + na][h * 2 + cc] + ccj0[col] + civ;
                                    rowacc[rr] += ex2(tv);
                                    if (q > p) g_Dpair[c][p][q] = ex2(-tv);
                                }
                            }
                    }
            }

            __syncthreads();
            float* red = reinterpret_cast<float*>(sm + OFF_BH0);
#pragma unroll
            for (int am = 0; am < 4; ++am)
#pragma unroll
                for (int h = 0; h < 2; ++h) {
                    int mloc = warp_m * 64 + am * 16 + h * 8 + gq;
                    red[mloc * 17 + warp_n * 4 + t] = rowacc[am * 2 + h];
                }
            __syncthreads();
            if (tid < BM && ri + tid < m) {
                float s = 0.f;
#pragma unroll
                for (int q = 0; q < 16; ++q) s += red[tid * 17 + q];
                g_S[base + ri + tid] = s;
            }
        }
        return;
    }

    // ======== z strip path ========
    const int bi = blockIdx.x;
    const int gr = blockIdx.y - 1;
    if (bi >= KT * gr + KT) return;
    const int lo = (bi > KT * gr) ? bi : KT * gr;
    const int hi = KT * gr + KT;

    const int r0 = bi * BM;
    const uint32_t bufB[2] = {smb + OFF_BH0, smb + OFF_BH1};
    float* ccjb[2] = {ccj0, ccj1};

    for (int s = tid; s < 2048; s += 256) {
        int row = s >> 4, ch = s & 15;
        CP_ASYNC16(smb + OFF_AH + (uint32_t)(row * PITCHB + ch * 16),
                   g_embA + (size_t)(r0 + row) * DIM + ch * 8);
    }
    if (tid < BM) rci[tid] = g_csqP[r0 + tid];

    for (int s = tid; s < 2048; s += 256) {
        int row = s >> 4, ch = s & 15;
        CP_ASYNC16(bufB[0] + (uint32_t)(row * PITCHB + ch * 16),
                   g_embB + (size_t)(lo * BM + row) * DIM + ch * 8);
    }
    if (tid < BM) ccj0[tid] = g_csqP[lo * BM + tid];
    CP_COMMIT();

    uint32_t rowacc2[8];
#pragma unroll
    for (int i = 0; i < 8; ++i) rowacc2[i] = 0u;

    for (int bj = lo; bj < hi; ++bj) {
        const int cur = (bj - lo) & 1;
        const int c0 = bj * BM;
        const bool offdiag = (bj != bi);

        if (bj + 1 < hi) {
            const int nc0 = (bj + 1) * BM;
            for (int s = tid; s < 2048; s += 256) {
                int row = s >> 4, ch = s & 15;
                CP_ASYNC16(bufB[cur ^ 1] + (uint32_t)(row * PITCHB + ch * 16),
                           g_embB + (size_t)(nc0 + row) * DIM + ch * 8);
            }
            if (tid < BM) ccjb[cur ^ 1][tid] = g_csqP[nc0 + tid];
            CP_COMMIT();
            CP_WAIT(1);
        } else {
            CP_WAIT(0);
        }
        __syncthreads();

        const uint32_t aBh = bufB[cur] + boff;
        const float* ccj = ccjb[cur];

        float acc[16][4];
#pragma unroll
        for (int i = 0; i < 16; ++i)
#pragma unroll
            for (int j = 0; j < 4; ++j) acc[i][j] = 0.f;

#pragma unroll
        for (int ks = 0; ks < 8; ++ks) {
            const uint32_t kb = (uint32_t)ks * 32;
            uint32_t ah[4][4], bh[2][4];
#pragma unroll
            for (int am = 0; am < 4; ++am)
                LDSM4(ah[am], aAh + (uint32_t)am * (16 * PITCHB) + kb);
#pragma unroll
            for (int bn = 0; bn < 2; ++bn)
                LDSM4(bh[bn], aBh + (uint32_t)bn * (16 * PITCHB) + kb);
#pragma unroll
            for (int am = 0; am < 4; ++am)
#pragma unroll
                for (int na = 0; na < 4; ++na) {
                    const int bn = na >> 1, p = (na & 1) * 2;
                    mma16816(acc[am * 4 + na], ah[am], bh[bn][p], bh[bn][p + 1]);
                }
        }

        uint32_t colacc2[4] = {0u, 0u, 0u, 0u};
        float cjv[8];
#pragma unroll
        for (int na = 0; na < 4; ++na)
#pragma unroll
            for (int cc = 0; cc < 2; ++cc)
                cjv[na * 2 + cc] = ccj[warp_n * 32 + na * 8 + 2 * t + cc];

#pragma unroll
        for (int am = 0; am < 4; ++am)
#pragma unroll
            for (int h = 0; h < 2; ++h) {
                const int rr = am * 2 + h;
                const float civ = rci[warp_m * 64 + am * 16 + h * 8 + gq];
                float pc[8];
#pragma unroll
                for (int i = 0; i < 8; ++i) pc[i] = cjv[i] + civ;
                uint32_t racc2 = rowacc2[rr];
#pragma unroll
                for (int na = 0; na < 4; ++na) {
                    float tv0 = acc[am * 4 + na][h * 2 + 0] + pc[na * 2 + 0];
                    float tv1 = acc[am * 4 + na][h * 2 + 1] + pc[na * 2 + 1];
                    uint32_t e2 = pack_ex2_f16x2(tv1, tv0);
                    racc2 = hadd2u(racc2, e2);
                    colacc2[na] = hadd2u(colacc2[na], e2);
                }
                rowacc2[rr] = racc2;
            }

        if (offdiag) {
#pragma unroll
            for (int i = 0; i < 4; ++i)
#pragma unroll
                for (int off = 4; off < 32; off <<= 1)
                    colacc2[i] = hadd2u(colacc2[i],
                                        __shfl_xor_sync(0xffffffffu, colacc2[i], off));
            if (warp_m == 0 && gq == 0) {
#pragma unroll
                for (int na = 0; na < 4; ++na)
                    colred2[warp_n * 16 + na * 4 + t] = colacc2[na];
            }
        }
        __syncthreads();
        if (offdiag && warp_m == 1 && gq == 0) {
#pragma unroll
            for (int na = 0; na < 4; ++na) {
                uint32_t s2 = hadd2u(colred2[warp_n * 16 + na * 4 + t], colacc2[na]);
                float2 f = f16x2_to_f2(s2);
                int col = warp_n * 32 + na * 8 + 2 * t;
                g_Zmat[c0 + col][bi]     = f.x;   // transposed layout
                g_Zmat[c0 + col + 1][bi] = f.y;
            }
        }
    }

    __syncthreads();
    float* red = reinterpret_cast<float*>(sm + OFF_BH0);
#pragma unroll
    for (int am = 0; am < 4; ++am)
#pragma unroll
        for (int h = 0; h < 2; ++h) {
            int mloc = warp_m * 64 + am * 16 + h * 8 + gq;
            float2 f = f16x2_to_f2(rowacc2[am * 2 + h]);
            red[mloc * 17 + warp_n * 4 + t] = f.x + f.y;
        }
    __syncthreads();
    if (tid < BM) {
        float s = 0.f;
#pragma unroll
        for (int q = 0; q < 16; ++q) s += red[tid * 17 + q];
        g_Zmat[r0 + tid][NT + gr] = s;   // transposed layout
    }
}

// ---------------- pair kernel: warp per slot, coalesced Za read ----------------
__global__ __launch_bounds__(256)
void pair3_kernel() {
    const int s    = (blockIdx.x * blockDim.x + threadIdx.x) >> 5;
    const int lane = threadIdx.x & 31;
    const int c = g_slotcls[s];
    const int p = s - g_off[c];
    const int m = g_off[c + 1] - g_off[c];

    // coalesced: 72 contiguous floats per anchor row
    const float* zr = g_Zmat[s];
    float Za = zr[lane] + zr[lane + 32];
    if (lane < NGRP) Za += zr[NT + lane];
#pragma unroll
    for (int off = 16; off > 0; off >>= 1)
        Za += __shfl_xor_sync(0xffffffffu, Za, off);
    Za -= g_S[s];

    float lsum = 0.f;
    for (int q = p + 1 + lane; q < m; q += 32)
        lsum += lg2(fmaf(Za, g_Dpair[c][p][q], 1.0f));
    lsum *= LN2;
#pragma unroll
    for (int off = 16; off > 0; off >>= 1)
        lsum += __shfl_xor_sync(0xffffffffu, lsum, off);
    if (lane == 0) g_rowsum[s] = lsum;
}

// ---------------- finish ----------------
__global__ __launch_bounds__(512)
void finish_kernel(float* __restrict__ out) {
    __shared__ float smean[NCLS];
    __shared__ int   svalid[NCLS];
    const int tid = threadIdx.x, warp = tid >> 5, lane = tid & 31;

    for (int c = warp * 4; c < warp * 4 + 4; ++c) {
        const int base = g_off[c];
        const int m = g_off[c + 1] - base;
        float s = 0.f;
        for (int q = lane; q < m; q += 32) s += g_rowsum[base + q];
#pragma unroll
        for (int off = 16; off > 0; off >>= 1)
            s += __shfl_xor_sync(0xffffffffu, s, off);
        if (lane == 0) {
            if (m >= 2) {
                smean[c]  = s / (0.5f * (float)m * (float)(m - 1));
                svalid[c] = 1;
            } else { smean[c] = 0.f; svalid[c] = 0; }
        }
    }
    __syncthreads();
    if (warp == 0) {
        float s  = smean[lane] + smean[lane + 32];
        int   nv = svalid[lane] + svalid[lane + 32];
#pragma unroll
        for (int off = 16; off > 0; off >>= 1) {
            s  += __shfl_xor_sync(0xffffffffu, s, off);
            nv += __shfl_xor_sync(0xffffffffu, nv, off);
        }
        if (lane == 0) out[0] = s / (float)(nv > 0 ? nv : 1);
    }
}

// ---------------- launch ----------------
extern "C" void kernel_launch(void* const* d_in, const int* in_sizes, int n_in,
                              void* d_out, int out_size) {
    const float* emb    = (const float*)d_in[0];
    const int*   labels = (const int*)d_in[1];
    float*       out    = (float*)d_out;

    static bool attr_set = false;
    if (!attr_set) {
        cudaFuncSetAttribute(zc_kernel, cudaFuncAttributeMaxDynamicSharedMemorySize, Z_SMEM_Z);
        attr_set = true;
    }

    classes_kernel<<<NCLS, 256>>>(labels);
    prep_kernel<<<N / 8, 256>>>(emb, labels);
    zc_kernel<<<dim3(NT, NGRP + 1), 256, Z_SMEM_Z>>>();
    pair3_kernel<<<N / 8, 256>>>();
    finish_kernel<<<1, 512>>>(out);
}